// round 5
// baseline (speedup 1.0000x reference)
#include <cuda_runtime.h>
#include <math.h>

#define Nn 4096
#define Ee 8192
#define Mm 128
#define ND 128
#define ED 64
#define PQ 16
#define NP (Nn*PQ)
#define LAYERS 4
#define TAU 0.25f
#define FRIC 0.1f
#define MAXD 32
#define INC_CAP 16384

// ---------------- device scratch (no allocation allowed) ----------------
__device__ float g_a[Nn], g_c[Nn], g_avt[Nn], g_avu[Nn];
__device__ float g_pd0[Nn], g_pwu[Nn], g_pn[Nn], g_qd0[Nn], g_Wn[Nn];
__device__ int   g_mol[Nn];
__device__ int   g_cnt[Nn];            // must be zero at k1 entry; reset in k5
__device__ int   g_adj[Nn * MAXD];     // (e<<12)|other
__device__ float g_winc[Nn * MAXD];    // per-slot edge weight
__device__ int   g_slotU[Ee], g_slotV[Ee];
__device__ float g_p0[NP], g_q0[NP];
__device__ float g_SA[Nn], g_SB[Nn], g_SC[Nn];

__device__ __forceinline__ float warp_sum(float v) {
#pragma unroll
    for (int o = 16; o; o >>= 1) v += __shfl_xor_sync(0xffffffffu, v, o);
    return v;
}
__device__ __forceinline__ float sigmoidf(float x) { return 1.f / (1.f + expf(-x)); }
__device__ __forceinline__ float softplusf(float x) { return fmaxf(x, 0.f) + log1pf(expf(-fabsf(x))); }

// ======== k1: node setup (warp/node) + mol ids + adjacency build ========
__global__ void k1(const float* __restrict__ vf, const float* __restrict__ mnm,
                   const int* __restrict__ us, const int* __restrict__ vs,
                   const float* __restrict__ We, const float* __restrict__ Wp,
                   const float* __restrict__ bp, const float* __restrict__ Wt,
                   const float* __restrict__ Wu)
{
    int tid  = blockIdx.x * blockDim.x + threadIdx.x;   // 131072 threads
    int lane = threadIdx.x & 31;
    int n    = tid >> 5;                                 // warp -> node

    if (tid < Nn) g_Wn[tid] = 0.f;

    for (int idx = tid; idx < Mm * Nn; idx += 131072)
        if (mnm[idx] > 0.5f) g_mol[idx & (Nn - 1)] = idx >> 12;

    for (int e = tid; e < Ee; e += 131072) {
        int u = us[e], v = vs[e];
        int s1 = atomicAdd(&g_cnt[u], 1);
        if (s1 < MAXD) g_adj[u * MAXD + s1] = (e << 12) | v;
        g_slotU[e] = s1;
        if (u != v) {
            int s2 = atomicAdd(&g_cnt[v], 1);
            if (s2 < MAXD) g_adj[v * MAXD + s2] = (e << 12) | u;
            g_slotV[e] = s2;
        }
    }

    float v0 = vf[n*ND+lane], v1 = vf[n*ND+lane+32], v2 = vf[n*ND+lane+64], v3 = vf[n*ND+lane+96];
    float sa = warp_sum(v0*We[lane]     + v1*We[lane+32]     + v2*We[lane+64]     + v3*We[lane+96]);
    float sc = warp_sum(v0*We[192+lane] + v1*We[192+lane+32] + v2*We[192+lane+64] + v3*We[192+lane+96]);
    float st = warp_sum(v0*Wt[lane]     + v1*Wt[lane+32]     + v2*Wt[lane+64]     + v3*Wt[lane+96]);
    float su = warp_sum(v0*Wu[lane]     + v1*Wu[lane+32]     + v2*Wu[lane+64]     + v3*Wu[lane+96]);

    float pk = 0.f;
#pragma unroll
    for (int k = 0; k < PQ; k++) {
        float s = warp_sum(v0*Wp[lane*PQ+k] + v1*Wp[(lane+32)*PQ+k] +
                           v2*Wp[(lane+64)*PQ+k] + v3*Wp[(lane+96)*PQ+k]);
        if (lane == k) pk = tanhf(s + bp[k]);
    }
    float pd0 = warp_sum(lane < PQ ? pk * Wt[ND+lane] : 0.f);
    float pwu = warp_sum(lane < PQ ? pk * Wu[ND+lane] : 0.f);
    float pn  = warp_sum(lane < PQ ? pk * pk          : 0.f);
    if (lane < PQ) g_p0[n*PQ+lane] = pk;
    if (lane == 0) {
        g_a[n] = sa; g_c[n] = sc; g_avt[n] = st; g_avu[n] = su;
        g_pd0[n] = pd0; g_pwu[n] = pwu; g_pn[n] = pn;
    }
}

// ======== k2: edge weights (warp/edge) ========
__global__ void k2(const float* __restrict__ ef,
                   const int* __restrict__ us, const int* __restrict__ vs,
                   const float* __restrict__ We, const float* __restrict__ be)
{
    int e    = (blockIdx.x * blockDim.x + threadIdx.x) >> 5;
    int lane = threadIdx.x & 31;
    if (e >= Ee) return;
    float s = ef[e*ED+lane] * We[128+lane] + ef[e*ED+32+lane] * We[160+lane];
    s = warp_sum(s);
    if (lane == 0) {
        int u = us[e], v = vs[e];
        float w = sigmoidf(g_a[u] + g_c[v] + s + be[0]);
        int s1 = g_slotU[e];
        if (s1 < MAXD) g_winc[u * MAXD + s1] = w;
        if (u != v) {
            int s2 = g_slotV[e];
            if (s2 < MAXD) g_winc[v * MAXD + s2] = w;
            atomicAdd(&g_Wn[u], w);
            atomicAdd(&g_Wn[v], w);
        }
    }
}

// ======== k3: q0 = tanh((e@v)@Wq + bq), qdot0 (warp/node) ========
__global__ void k3(const float* __restrict__ vf, const float* __restrict__ Wq,
                   const float* __restrict__ bq, const float* __restrict__ Wu)
{
    int n    = (blockIdx.x * blockDim.x + threadIdx.x) >> 5;
    int lane = threadIdx.x & 31;
    float x0 = vf[n*ND+lane], x1 = vf[n*ND+lane+32], x2 = vf[n*ND+lane+64], x3 = vf[n*ND+lane+96];
    float Wn = g_Wn[n];
    float e0 = Wn*x0, e1 = Wn*x1, e2 = Wn*x2, e3 = Wn*x3;
    int deg = min(g_cnt[n], MAXD);
    for (int j = 0; j < deg; j++) {
        int   o = g_adj[n*MAXD+j] & 0xFFF;
        float w = g_winc[n*MAXD+j];
        e0 += w * vf[o*ND+lane];
        e1 += w * vf[o*ND+lane+32];
        e2 += w * vf[o*ND+lane+64];
        e3 += w * vf[o*ND+lane+96];
    }
    float qk = 0.f;
#pragma unroll
    for (int k = 0; k < PQ; k++) {
        float s = warp_sum(e0*Wq[lane*PQ+k] + e1*Wq[(lane+32)*PQ+k] +
                           e2*Wq[(lane+64)*PQ+k] + e3*Wq[(lane+96)*PQ+k]);
        if (lane == k) qk = tanhf(s + bq[k]);
    }
    float qd0 = warp_sum(lane < PQ ? qk * Wu[ND+lane] : 0.f);
    if (lane < PQ) g_q0[n*PQ+lane] = qk;
    if (lane == 0) g_qd0[n] = qd0;
}

// ======== k4: 4 layers on scalar state, single block, SMEM-resident, no spills ========
// SMEM: incidence CSR (s_o u16 32KB + s_w f32 64KB) + 7 node arrays (112KB) + small = ~215KB
#define K4_SMEM (INC_CAP*2 + INC_CAP*4 + 7*Nn*4 + 8*Mm*4 + 2*Mm*4 + 64*4 + 40*4 + 32*4)
__global__ void __launch_bounds__(1024, 1)
k4(const float* __restrict__ Wt, const float* __restrict__ Wu, float* __restrict__ out)
{
    extern __shared__ char sm_raw[];
    unsigned short* s_o = (unsigned short*)sm_raw;          // INC_CAP
    float* s_w    = (float*)(s_o + INC_CAP);                // INC_CAP
    float* s_cumA = s_w + INC_CAP;                          // Nn
    float* s_cumB = s_cumA + Nn;                            // Nn
    float* s_su   = s_cumB + Nn;                            // Nn (prologue: qd0 temp)
    float* s_zub  = s_su + Nn;                              // Nn
    float* s_atp  = s_zub + Nn;                             // Nn  (avt + pd0)
    float* s_pd0  = s_atp + Nn;                             // Nn
    float* s_pwu  = s_pd0 + Nn;                             // Nn
    float* s_Gm   = s_pwu + Nn;                             // 4*Mm
    float* s_Sm   = s_Gm + 4*Mm;                            // 4*Mm
    float* s_h    = s_Sm + 4*Mm;                            // Mm
    float* s_d2   = s_h + Mm;                               // Mm
    float* s_red  = s_d2 + Mm;                              // 64
    float* s_slT  = s_red + 64;                             // 40 (per-layer totals + PN)
    int*   s_ib   = (int*)(s_slT + 40);                     // 32

    const int t = threadIdx.x, lane = t & 31, wp = t >> 5;

    float nWt = 0.f, nWu = 0.f, dTU = 0.f;
#pragma unroll
    for (int k = 0; k < PQ; k++) {
        float a = Wu[ND+k], b = Wt[ND+k];
        nWu += a*a; nWt += b*b; dTU += a*b;
    }

    for (int i = t; i < 4*Mm; i += 1024) { s_Gm[i] = 0.f; s_Sm[i] = 0.f; }
    if (t < Mm) { s_h[t] = 0.f; s_d2[t] = 0.f; }

    // ---- degree scan -> CSR offsets ----
    int deg[4], off[4];
    int tot = 0;
#pragma unroll
    for (int j = 0; j < 4; j++) { deg[j] = min(g_cnt[t + j*1024], MAXD); tot += deg[j]; }
    int pre = tot;
#pragma unroll
    for (int o = 1; o < 32; o <<= 1) { int v = __shfl_up_sync(0xffffffffu, pre, o); if (lane >= o) pre += v; }
    if (lane == 31) s_ib[wp] = pre;
    __syncthreads();
    if (wp == 0) {
        int v = s_ib[lane], p2 = v;
#pragma unroll
        for (int o = 1; o < 32; o <<= 1) { int x = __shfl_up_sync(0xffffffffu, p2, o); if (lane >= o) p2 += x; }
        s_ib[lane] = p2 - v;
    }
    __syncthreads();
    {
        int base = s_ib[wp] + (pre - tot);
#pragma unroll
        for (int j = 0; j < 4; j++) { off[j] = base; base += deg[j]; }
    }

    // ---- compact incidences + load node statics; qd0 into s_su temporarily ----
    int   mol[4];
    float Wn[4];
    float pnsum = 0.f;
#pragma unroll
    for (int j = 0; j < 4; j++) {
        int n = t + j*1024;
        Wn[j] = g_Wn[n]; mol[j] = g_mol[n];
        float pd0 = g_pd0[n];
        s_su[n]  = g_qd0[n];
        s_atp[n] = g_avt[n] + pd0;
        s_pd0[n] = pd0;
        s_pwu[n] = g_pwu[n];
        s_cumA[n] = 0.f;
        pnsum += g_pn[n];
        for (int x = 0; x < deg[j]; x++) {
            s_o[off[j]+x] = (unsigned short)(g_adj[n*MAXD+x] & 0xFFF);
            s_w[off[j]+x] = g_winc[n*MAXD+x];
        }
    }
    // reduce PN_tot (layer-invariant part of s-loss)
    pnsum = warp_sum(pnsum);
    if (lane == 0) s_red[wp] = pnsum;
    __syncthreads();
    if (t == 0) {
        float s = 0.f;
        for (int i = 0; i < 32; i++) s += s_red[i];
        s_slT[LAYERS] = s;
    }
    __syncthreads();

    // ---- zub = avu + Wn*qd0 + sum w*qd0[o]  (static gather) ----
#pragma unroll
    for (int j = 0; j < 4; j++) {
        int n = t + j*1024;
        float g = Wn[j] * s_su[n];
        for (int x = off[j]; x < off[j]+deg[j]; x++) g += s_w[x] * s_su[s_o[x]];
        s_zub[n] = g_avu[n] + g;
    }
    __syncthreads();

    // ---- layers: only cumSt evolves through gathers ----
    float cumGg[4] = {0,0,0,0};
    float wS[4] = {0,0,0,0}, wG[4] = {0,0,0,0};
    float slr[LAYERS];
    float* cur = s_cumA;
    float* nxt = s_cumB;
    for (int i = 0; i < LAYERS; i++) {
        // phase a: gather cumSt -> st, su
        for (int j = 0; j < 4; j++) {
            int n = t + j*1024;
            float cA = cur[n];
            float g = Wn[j] * cA;
            for (int x = off[j]; x < off[j]+deg[j]; x++) g += s_w[x] * cur[s_o[x]];
            float zu = s_zub[n] + TAU * dTU * g;
            float zt = s_atp[n] - TAU * (dTU * cumGg[j] + FRIC * nWt * cA);
            float st = sigmoidf(zt), su = sigmoidf(zu);
            s_su[n] = su;
            nxt[n] = cA + st;
            atomicAdd(&s_Sm[i*Mm + mol[j]], st);
            if (i == LAYERS-1) {
                atomicAdd(&s_h[mol[j]], softplusf(zt) + softplusf(zu));
                atomicAdd(&s_d2[mol[j]], st * st);
            }
        }
        __syncthreads();
        // phase b: gather su -> gg, losses, weighted sums
        float slp = 0.f;
        float lw = (float)(LAYERS - i);
        for (int j = 0; j < 4; j++) {
            int n = t + j*1024;
            float su = s_su[n];
            float cA = cur[n];
            float st = nxt[n] - cA;
            float gg = Wn[j] * su;
            for (int x = off[j]; x < off[j]+deg[j]; x++) gg += s_w[x] * s_su[s_o[x]];
            float alpha = st + TAU * FRIC * cA;
            float beta  = TAU * cumGg[j];
            slp += alpha*alpha*nWt + beta*beta*nWu + 2.f*alpha*beta*dTU
                 - 2.f*alpha*s_pd0[n] - 2.f*beta*s_pwu[n];
            atomicAdd(&s_Gm[i*Mm + mol[j]], gg);
            cumGg[j] += gg;
            wS[j] += lw * st;
            wG[j] += lw * gg;
        }
        slr[i] = slp;
        __syncthreads();
        float* tmp = cur; cur = nxt; nxt = tmp;
    }

    // ---- write final-average coefficients ----
#pragma unroll
    for (int j = 0; j < 4; j++) {
        int n = t + j*1024;
        g_SA[n] = -(TAU*FRIC) * wS[j];
        g_SB[n] = -TAU * wG[j];
        g_SC[n] =  TAU * wS[j];
    }

    // ---- reduce s-losses per layer ----
    for (int i = 0; i < LAYERS; i++) {
        float r = warp_sum(slr[i]);
        if (lane == 0) s_red[wp] = r;
        __syncthreads();
        if (wp == 0) {
            float v = warp_sum(s_red[lane]);
            if (lane == 0) s_slT[i] = v + s_slT[LAYERS];
        }
        __syncthreads();
    }

    if (t < 32) {
        float cT = 0.f;
        for (int i = 0; i < LAYERS; i++) {
            float term = 0.f;
            for (int m = lane; m < Mm; m += 32) {
                float Gm = s_Gm[i*Mm+m], Sm = s_Sm[i*Mm+m];
                term += Gm*Gm*nWu + 2.f*FRIC*Gm*Sm*dTU + FRIC*FRIC*Sm*Sm*nWt;
            }
            term = warp_sum(term);
            cT += TAU * sqrtf(term);
        }
        if (lane == 0) {
            float sT = 0.f;
            for (int i = 0; i < LAYERS; i++) sT += sqrtf(s_slT[i]);
            out[2*NP + 0] = sT;
            out[2*NP + 1] = cT;
        }
    }
    if (t < Mm) {
        out[2*NP + 2 + t]      = s_h[t];
        out[2*NP + 2 + Mm + t] = s_d2[t] * nWt;
    }
}

// ======== k5: expand outputs, reset counters ========
__global__ void k5(const float* __restrict__ Wt, const float* __restrict__ Wu,
                   float* __restrict__ out)
{
    int idx = blockIdx.x * blockDim.x + threadIdx.x;  // 131072 = 2*NP
    if (idx < NP) {
        int n = idx >> 4, k = idx & 15;
        out[idx] = 0.2f * (5.f*g_p0[idx] + g_SA[n]*Wt[ND+k] + g_SB[n]*Wu[ND+k]);
    } else {
        int id2 = idx - NP, n = id2 >> 4, k = id2 & 15;
        out[idx] = 0.2f * (5.f*g_q0[id2] + g_SC[n]*Wt[ND+k]);
    }
    if (idx < Nn) g_cnt[idx] = 0;
}

extern "C" void kernel_launch(void* const* d_in, const int* in_sizes, int n_in,
                              void* d_out, int out_size)
{
    const float* vf  = (const float*)d_in[0];
    const float* ef  = (const float*)d_in[1];
    const int*   us  = (const int*)  d_in[2];
    const int*   vs  = (const int*)  d_in[3];
    const float* mnm = (const float*)d_in[4];
    const float* We  = (const float*)d_in[8];
    const float* be  = (const float*)d_in[9];
    const float* Wp  = (const float*)d_in[10];
    const float* bp  = (const float*)d_in[11];
    const float* Wq  = (const float*)d_in[12];
    const float* bq  = (const float*)d_in[13];
    const float* Wt  = (const float*)d_in[14];
    const float* Wu  = (const float*)d_in[15];
    float* out = (float*)d_out;

    cudaFuncSetAttribute(k4, cudaFuncAttributeMaxDynamicSharedMemorySize, K4_SMEM);

    k1<<<512, 256>>>(vf, mnm, us, vs, We, Wp, bp, Wt, Wu);
    k2<<<1024, 256>>>(ef, us, vs, We, be);
    k3<<<512, 256>>>(vf, Wq, bq, Wu);
    k4<<<1, 1024, K4_SMEM>>>(Wt, Wu, out);
    k5<<<512, 256>>>(Wt, Wu, out);
}

// round 6
// speedup vs baseline: 1.0409x; 1.0409x over previous
#include <cuda_runtime.h>
#include <math.h>

#define Nn 4096
#define Ee 8192
#define Mm 128
#define ND 128
#define ED 64
#define PQ 16
#define NP (Nn*PQ)
#define LAYERS 4
#define TAU 0.25f
#define FRIC 0.1f
#define MAXD 32
#define INC_CAP 16384

// ---------------- device scratch (no allocation allowed) ----------------
__device__ float g_a[Nn], g_c[Nn], g_avt[Nn], g_avu[Nn];
__device__ float g_pd0[Nn], g_pwu[Nn], g_pn[Nn], g_qd0[Nn], g_Wn[Nn];
__device__ int   g_mol[Nn];
__device__ int   g_cnt[Nn];            // must be zero at k1 entry; reset in k5
__device__ int   g_adj[Nn * MAXD];     // (e<<12)|other
__device__ float g_winc[Nn * MAXD];    // per-slot edge weight
__device__ int   g_slotU[Ee], g_slotV[Ee];
__device__ float g_p0[NP], g_q0[NP];
__device__ float g_SA[Nn], g_SB[Nn], g_SC[Nn];

__device__ __forceinline__ float warp_sum(float v) {
#pragma unroll
    for (int o = 16; o; o >>= 1) v += __shfl_xor_sync(0xffffffffu, v, o);
    return v;
}
__device__ __forceinline__ float sigmoidf(float x) { return 1.f / (1.f + expf(-x)); }
__device__ __forceinline__ float softplusf(float x) { return fmaxf(x, 0.f) + log1pf(expf(-fabsf(x))); }

// ======== k1: node setup (warp/node) + mol ids + adjacency build ========
__global__ void k1(const float* __restrict__ vf, const float* __restrict__ mnm,
                   const int* __restrict__ us, const int* __restrict__ vs,
                   const float* __restrict__ We, const float* __restrict__ Wp,
                   const float* __restrict__ bp, const float* __restrict__ Wt,
                   const float* __restrict__ Wu)
{
    int tid  = blockIdx.x * blockDim.x + threadIdx.x;   // 131072 threads
    int lane = threadIdx.x & 31;
    int n    = tid >> 5;                                 // warp -> node

    if (tid < Nn) g_Wn[tid] = 0.f;

    for (int idx = tid; idx < Mm * Nn; idx += 131072)
        if (mnm[idx] > 0.5f) g_mol[idx & (Nn - 1)] = idx >> 12;

    for (int e = tid; e < Ee; e += 131072) {
        int u = us[e], v = vs[e];
        int s1 = atomicAdd(&g_cnt[u], 1);
        if (s1 < MAXD) g_adj[u * MAXD + s1] = (e << 12) | v;
        g_slotU[e] = s1;
        if (u != v) {
            int s2 = atomicAdd(&g_cnt[v], 1);
            if (s2 < MAXD) g_adj[v * MAXD + s2] = (e << 12) | u;
            g_slotV[e] = s2;
        }
    }

    float v0 = vf[n*ND+lane], v1 = vf[n*ND+lane+32], v2 = vf[n*ND+lane+64], v3 = vf[n*ND+lane+96];
    float sa = warp_sum(v0*We[lane]     + v1*We[lane+32]     + v2*We[lane+64]     + v3*We[lane+96]);
    float sc = warp_sum(v0*We[192+lane] + v1*We[192+lane+32] + v2*We[192+lane+64] + v3*We[192+lane+96]);
    float st = warp_sum(v0*Wt[lane]     + v1*Wt[lane+32]     + v2*Wt[lane+64]     + v3*Wt[lane+96]);
    float su = warp_sum(v0*Wu[lane]     + v1*Wu[lane+32]     + v2*Wu[lane+64]     + v3*Wu[lane+96]);

    float pk = 0.f;
#pragma unroll
    for (int k = 0; k < PQ; k++) {
        float s = warp_sum(v0*Wp[lane*PQ+k] + v1*Wp[(lane+32)*PQ+k] +
                           v2*Wp[(lane+64)*PQ+k] + v3*Wp[(lane+96)*PQ+k]);
        if (lane == k) pk = tanhf(s + bp[k]);
    }
    float pd0 = warp_sum(lane < PQ ? pk * Wt[ND+lane] : 0.f);
    float pwu = warp_sum(lane < PQ ? pk * Wu[ND+lane] : 0.f);
    float pn  = warp_sum(lane < PQ ? pk * pk          : 0.f);
    if (lane < PQ) g_p0[n*PQ+lane] = pk;
    if (lane == 0) {
        g_a[n] = sa; g_c[n] = sc; g_avt[n] = st; g_avu[n] = su;
        g_pd0[n] = pd0; g_pwu[n] = pwu; g_pn[n] = pn;
    }
}

// ======== k2: edge weights (warp/edge) ========
__global__ void k2(const float* __restrict__ ef,
                   const int* __restrict__ us, const int* __restrict__ vs,
                   const float* __restrict__ We, const float* __restrict__ be)
{
    int e    = (blockIdx.x * blockDim.x + threadIdx.x) >> 5;
    int lane = threadIdx.x & 31;
    if (e >= Ee) return;
    float s = ef[e*ED+lane] * We[128+lane] + ef[e*ED+32+lane] * We[160+lane];
    s = warp_sum(s);
    if (lane == 0) {
        int u = us[e], v = vs[e];
        float w = sigmoidf(g_a[u] + g_c[v] + s + be[0]);
        int s1 = g_slotU[e];
        if (s1 < MAXD) g_winc[u * MAXD + s1] = w;
        if (u != v) {
            int s2 = g_slotV[e];
            if (s2 < MAXD) g_winc[v * MAXD + s2] = w;
            atomicAdd(&g_Wn[u], w);
            atomicAdd(&g_Wn[v], w);
        }
    }
}

// ======== k3: q0 = tanh((e@v)@Wq + bq), qdot0 (warp/node) ========
__global__ void k3(const float* __restrict__ vf, const float* __restrict__ Wq,
                   const float* __restrict__ bq, const float* __restrict__ Wu)
{
    int n    = (blockIdx.x * blockDim.x + threadIdx.x) >> 5;
    int lane = threadIdx.x & 31;
    float x0 = vf[n*ND+lane], x1 = vf[n*ND+lane+32], x2 = vf[n*ND+lane+64], x3 = vf[n*ND+lane+96];
    float Wn = g_Wn[n];
    float e0 = Wn*x0, e1 = Wn*x1, e2 = Wn*x2, e3 = Wn*x3;
    int deg = min(g_cnt[n], MAXD);
    for (int j = 0; j < deg; j++) {
        int   o = g_adj[n*MAXD+j] & 0xFFF;
        float w = g_winc[n*MAXD+j];
        e0 += w * vf[o*ND+lane];
        e1 += w * vf[o*ND+lane+32];
        e2 += w * vf[o*ND+lane+64];
        e3 += w * vf[o*ND+lane+96];
    }
    float qk = 0.f;
#pragma unroll
    for (int k = 0; k < PQ; k++) {
        float s = warp_sum(e0*Wq[lane*PQ+k] + e1*Wq[(lane+32)*PQ+k] +
                           e2*Wq[(lane+64)*PQ+k] + e3*Wq[(lane+96)*PQ+k]);
        if (lane == k) qk = tanhf(s + bq[k]);
    }
    float qd0 = warp_sum(lane < PQ ? qk * Wu[ND+lane] : 0.f);
    if (lane < PQ) g_q0[n*PQ+lane] = qk;
    if (lane == 0) g_qd0[n] = qd0;
}

// ======== k4: 4 layers on scalar state, single block, SMEM-resident ========
// ALL per-node register arrays are touched only inside fully-unrolled loops so
// they stay in registers (runtime-indexed arrays in rolled loops => local mem).
#define K4_SMEM (INC_CAP*2 + INC_CAP*4 + 7*Nn*4 + 8*Mm*4 + 2*Mm*4 + 64*4 + 40*4 + 32*4)
__global__ void __launch_bounds__(1024, 1)
k4(const float* __restrict__ Wt, const float* __restrict__ Wu, float* __restrict__ out)
{
    extern __shared__ char sm_raw[];
    unsigned short* s_o = (unsigned short*)sm_raw;          // INC_CAP
    float* s_w    = (float*)(s_o + INC_CAP);                // INC_CAP
    float* s_cumA = s_w + INC_CAP;                          // Nn
    float* s_cumB = s_cumA + Nn;                            // Nn
    float* s_su   = s_cumB + Nn;                            // Nn (prologue: qd0 temp)
    float* s_zub  = s_su + Nn;                              // Nn
    float* s_atp  = s_zub + Nn;                             // Nn  (avt + pd0)
    float* s_pd0  = s_atp + Nn;                             // Nn
    float* s_pwu  = s_pd0 + Nn;                             // Nn
    float* s_Gm   = s_pwu + Nn;                             // 4*Mm
    float* s_Sm   = s_Gm + 4*Mm;                            // 4*Mm
    float* s_h    = s_Sm + 4*Mm;                            // Mm
    float* s_d2   = s_h + Mm;                               // Mm
    float* s_red  = s_d2 + Mm;                              // 64
    float* s_slT  = s_red + 64;                             // 40
    int*   s_ib   = (int*)(s_slT + 40);                     // 32

    const int t = threadIdx.x, lane = t & 31, wp = t >> 5;

    float nWt = 0.f, nWu = 0.f, dTU = 0.f;
#pragma unroll
    for (int k = 0; k < PQ; k++) {
        float a = Wu[ND+k], b = Wt[ND+k];
        nWu += a*a; nWt += b*b; dTU += a*b;
    }

    for (int i = t; i < 4*Mm; i += 1024) { s_Gm[i] = 0.f; s_Sm[i] = 0.f; }
    if (t < Mm) { s_h[t] = 0.f; s_d2[t] = 0.f; }

    // ---- degree scan -> CSR offsets (all j loops unrolled) ----
    int deg[4], off[4], end_[4];
    int tot = 0;
#pragma unroll
    for (int j = 0; j < 4; j++) { deg[j] = min(g_cnt[t + j*1024], MAXD); tot += deg[j]; }
    int pre = tot;
#pragma unroll
    for (int o = 1; o < 32; o <<= 1) { int v = __shfl_up_sync(0xffffffffu, pre, o); if (lane >= o) pre += v; }
    if (lane == 31) s_ib[wp] = pre;
    __syncthreads();
    if (wp == 0) {
        int v = s_ib[lane], p2 = v;
#pragma unroll
        for (int o = 1; o < 32; o <<= 1) { int x = __shfl_up_sync(0xffffffffu, p2, o); if (lane >= o) p2 += x; }
        s_ib[lane] = p2 - v;
    }
    __syncthreads();
    {
        int base = s_ib[wp] + (pre - tot);
#pragma unroll
        for (int j = 0; j < 4; j++) { off[j] = base; base += deg[j]; end_[j] = base; }
    }

    // ---- compact incidences + load node statics; qd0 into s_su temporarily ----
    int   mol[4];
    float Wn[4];
    float pnsum = 0.f;
#pragma unroll
    for (int j = 0; j < 4; j++) {
        int n = t + j*1024;
        Wn[j] = g_Wn[n]; mol[j] = g_mol[n];
        float pd0 = g_pd0[n];
        s_su[n]  = g_qd0[n];
        s_atp[n] = g_avt[n] + pd0;
        s_pd0[n] = pd0;
        s_pwu[n] = g_pwu[n];
        s_cumA[n] = 0.f;
        pnsum += g_pn[n];
        for (int x = 0; x < deg[j]; x++) {
            s_o[off[j]+x] = (unsigned short)(g_adj[n*MAXD+x] & 0xFFF);
            s_w[off[j]+x] = g_winc[n*MAXD+x];
        }
    }
    pnsum = warp_sum(pnsum);
    if (lane == 0) s_red[wp] = pnsum;
    __syncthreads();
    if (t == 0) {
        float s = 0.f;
        for (int i = 0; i < 32; i++) s += s_red[i];
        s_slT[LAYERS] = s;
    }
    __syncthreads();

    // ---- zub = avu + Wn*qd0 + sum w*qd0[o] ----
#pragma unroll
    for (int j = 0; j < 4; j++) {
        int n = t + j*1024;
        float g = Wn[j] * s_su[n];
        for (int x = off[j]; x < end_[j]; x++) g += s_w[x] * s_su[s_o[x]];
        s_zub[n] = g_avu[n] + g;
    }
    __syncthreads();

    // ---- layers (fully unrolled; cumSt evolves through gathers) ----
    float cumGg[4] = {0,0,0,0};
    float wS[4] = {0,0,0,0}, wG[4] = {0,0,0,0};
    float slr[LAYERS];
    float* cur = s_cumA;
    float* nxt = s_cumB;
#pragma unroll
    for (int i = 0; i < LAYERS; i++) {
        // phase a: gather cumSt -> st, su
#pragma unroll
        for (int j = 0; j < 4; j++) {
            int n = t + j*1024;
            float cA = cur[n];
            float g = Wn[j] * cA;
            for (int x = off[j]; x < end_[j]; x++) g += s_w[x] * cur[s_o[x]];
            float zu = s_zub[n] + TAU * dTU * g;
            float zt = s_atp[n] - TAU * (dTU * cumGg[j] + FRIC * nWt * cA);
            float st = sigmoidf(zt), su = sigmoidf(zu);
            s_su[n] = su;
            nxt[n] = cA + st;
            atomicAdd(&s_Sm[i*Mm + mol[j]], st);
            if (i == LAYERS-1) {
                atomicAdd(&s_h[mol[j]], softplusf(zt) + softplusf(zu));
                atomicAdd(&s_d2[mol[j]], st * st);
            }
        }
        __syncthreads();
        // phase b: gather su -> gg, losses, weighted sums
        float slp = 0.f;
        const float lw = (float)(LAYERS - i);
#pragma unroll
        for (int j = 0; j < 4; j++) {
            int n = t + j*1024;
            float su = s_su[n];
            float cA = cur[n];
            float st = nxt[n] - cA;
            float gg = Wn[j] * su;
            for (int x = off[j]; x < end_[j]; x++) gg += s_w[x] * s_su[s_o[x]];
            float alpha = st + TAU * FRIC * cA;
            float beta  = TAU * cumGg[j];
            slp += alpha*alpha*nWt + beta*beta*nWu + 2.f*alpha*beta*dTU
                 - 2.f*alpha*s_pd0[n] - 2.f*beta*s_pwu[n];
            atomicAdd(&s_Gm[i*Mm + mol[j]], gg);
            cumGg[j] += gg;
            wS[j] += lw * st;
            wG[j] += lw * gg;
        }
        slr[i] = slp;
        __syncthreads();
        float* tmp = cur; cur = nxt; nxt = tmp;
    }

    // ---- write final-average coefficients ----
#pragma unroll
    for (int j = 0; j < 4; j++) {
        int n = t + j*1024;
        g_SA[n] = -(TAU*FRIC) * wS[j];
        g_SB[n] = -TAU * wG[j];
        g_SC[n] =  TAU * wS[j];
    }

    // ---- reduce s-losses per layer ----
#pragma unroll
    for (int i = 0; i < LAYERS; i++) {
        float r = warp_sum(slr[i]);
        if (lane == 0) s_red[wp] = r;
        __syncthreads();
        if (wp == 0) {
            float v = warp_sum(s_red[lane]);
            if (lane == 0) s_slT[i] = v + s_slT[LAYERS];
        }
        __syncthreads();
    }

    if (t < 32) {
        float cT = 0.f;
#pragma unroll
        for (int i = 0; i < LAYERS; i++) {
            float term = 0.f;
            for (int m = lane; m < Mm; m += 32) {
                float Gm = s_Gm[i*Mm+m], Sm = s_Sm[i*Mm+m];
                term += Gm*Gm*nWu + 2.f*FRIC*Gm*Sm*dTU + FRIC*FRIC*Sm*Sm*nWt;
            }
            term = warp_sum(term);
            cT += TAU * sqrtf(term);
        }
        if (lane == 0) {
            float sT = 0.f;
#pragma unroll
            for (int i = 0; i < LAYERS; i++) sT += sqrtf(s_slT[i]);
            out[2*NP + 0] = sT;
            out[2*NP + 1] = cT;
        }
    }
    if (t < Mm) {
        out[2*NP + 2 + t]      = s_h[t];
        out[2*NP + 2 + Mm + t] = s_d2[t] * nWt;
    }
}

// ======== k5: expand outputs, reset counters ========
__global__ void k5(const float* __restrict__ Wt, const float* __restrict__ Wu,
                   float* __restrict__ out)
{
    int idx = blockIdx.x * blockDim.x + threadIdx.x;  // 131072 = 2*NP
    if (idx < NP) {
        int n = idx >> 4, k = idx & 15;
        out[idx] = 0.2f * (5.f*g_p0[idx] + g_SA[n]*Wt[ND+k] + g_SB[n]*Wu[ND+k]);
    } else {
        int id2 = idx - NP, n = id2 >> 4, k = id2 & 15;
        out[idx] = 0.2f * (5.f*g_q0[id2] + g_SC[n]*Wt[ND+k]);
    }
    if (idx < Nn) g_cnt[idx] = 0;
}

extern "C" void kernel_launch(void* const* d_in, const int* in_sizes, int n_in,
                              void* d_out, int out_size)
{
    const float* vf  = (const float*)d_in[0];
    const float* ef  = (const float*)d_in[1];
    const int*   us  = (const int*)  d_in[2];
    const int*   vs  = (const int*)  d_in[3];
    const float* mnm = (const float*)d_in[4];
    const float* We  = (const float*)d_in[8];
    const float* be  = (const float*)d_in[9];
    const float* Wp  = (const float*)d_in[10];
    const float* bp  = (const float*)d_in[11];
    const float* Wq  = (const float*)d_in[12];
    const float* bq  = (const float*)d_in[13];
    const float* Wt  = (const float*)d_in[14];
    const float* Wu  = (const float*)d_in[15];
    float* out = (float*)d_out;

    cudaFuncSetAttribute(k4, cudaFuncAttributeMaxDynamicSharedMemorySize, K4_SMEM);

    k1<<<512, 256>>>(vf, mnm, us, vs, We, Wp, bp, Wt, Wu);
    k2<<<1024, 256>>>(ef, us, vs, We, be);
    k3<<<512, 256>>>(vf, Wq, bq, Wu);
    k4<<<1, 1024, K4_SMEM>>>(Wt, Wu, out);
    k5<<<512, 256>>>(Wt, Wu, out);
}